// round 5
// baseline (speedup 1.0000x reference)
#include <cuda_runtime.h>
#include <cstdint>
#include <cstddef>

#define N_   10000
#define E_   320000
#define HID_ 128
#define Z_   64
#define H_   4
#define EP_  (E_ + N_)

// ---------------- scratch (device globals; no allocation allowed) ----------------
__device__ float    g_h0 [N_*HID_];      // x @ gcn_w
__device__ float    g_acc[N_*HID_];      // GCN aggregation
__device__ float    g_h1 [N_*HID_];      // relu(acc + gcn_b)
__device__ float    g_gbuf[N_*H_*HID_];  // h1 @ gat_w   [n, h*128+d]
__device__ float    g_asrc[N_*H_];
__device__ float    g_adst[N_*H_];
__device__ unsigned g_emaxu[N_*H_];
__device__ float    g_emax[N_*H_];
__device__ float    g_den[N_*H_];        // later holds 0.25/den
__device__ float    g_ex [EP_*H_];       // self loop edge i stored at (E_+i)
__device__ float    g_agg[N_*HID_];
__device__ float    g_h2 [N_*HID_];
__device__ float    g_h3 [N_*HID_];
__device__ float    g_h4 [N_*HID_];
__device__ float    g_mu [N_*Z_];
__device__ float    g_lv [N_*Z_];
__device__ float    g_zb [N_*Z_];
__device__ float    g_d1 [N_*HID_];
__device__ float    g_db [N_*Z_];
__device__ float    g_deg [N_];
__device__ float    g_dinv[N_];

// ---------------- helpers ----------------
__device__ __forceinline__ unsigned fenc(float f) {
    unsigned u = __float_as_uint(f);
    return (u & 0x80000000u) ? ~u : (u | 0x80000000u);
}
__device__ __forceinline__ float fdec(unsigned x) {
    unsigned u = (x & 0x80000000u) ? (x ^ 0x80000000u) : ~x;
    return __uint_as_float(u);
}

// ---------------- init: deg=1 (self loop), emax=-FLT_MAX(enc), den=0 ----------------
__global__ void k_init() {
    int i = blockIdx.x * blockDim.x + threadIdx.x;
    if (i < N_) g_deg[i] = 1.0f;
    if (i < N_*H_) { g_emaxu[i] = 0x00800000u; g_den[i] = 0.0f; }
}

__global__ void k_deg(const int* __restrict__ dst) {
    int e = blockIdx.x * blockDim.x + threadIdx.x;
    if (e < E_) atomicAdd(&g_deg[dst[e]], 1.0f);
}

__global__ void k_dinv() {
    int i = blockIdx.x * blockDim.x + threadIdx.x;
    if (i < N_) g_dinv[i] = rsqrtf(g_deg[i]);
}

// GCN self-loop contribution, direct write (no atomics)
__global__ void k_gcn_self() {
    int idx = blockIdx.x * blockDim.x + threadIdx.x;
    if (idx >= N_*32) return;
    int node = idx >> 5, lane = idx & 31;
    float c = g_dinv[node]; c = c * c;
    float4 v = ((const float4*)(g_h0 + (size_t)node*HID_))[lane];
    v.x *= c; v.y *= c; v.z *= c; v.w *= c;
    ((float4*)(g_acc + (size_t)node*HID_))[lane] = v;
}

// GCN edge scatter: warp per edge, float4 vector atomics (sm_90+)
__global__ void k_gcn_scatter(const int* __restrict__ src, const int* __restrict__ dst) {
    int gi = blockIdx.x * blockDim.x + threadIdx.x;
    int e = gi >> 5, lane = gi & 31;
    if (e >= E_) return;
    int s = src[e], t = dst[e];
    float c = g_dinv[s] * g_dinv[t];
    float4 v = ((const float4*)(g_h0 + (size_t)s*HID_))[lane];
    v.x *= c; v.y *= c; v.z *= c; v.w *= c;
    atomicAdd(((float4*)(g_acc + (size_t)t*HID_)) + lane, v);
}

__global__ void k_bias_relu(const float* __restrict__ in, float* __restrict__ out,
                            const float* __restrict__ b, int total, int cmask) {
    int i = blockIdx.x * blockDim.x + threadIdx.x;
    if (i >= total) return;
    float v = in[i] + b[i & cmask];
    out[i] = fmaxf(v, 0.0f);
}

// attention logits per (node, head)
__global__ void k_att(const float* __restrict__ att_s, const float* __restrict__ att_d) {
    int i = blockIdx.x * blockDim.x + threadIdx.x;
    if (i >= N_*H_) return;
    int h = i & (H_-1);
    const float4* gr = (const float4*)(g_gbuf + (size_t)i*HID_);
    const float4* as4 = (const float4*)(att_s + h*HID_);
    const float4* ad4 = (const float4*)(att_d + h*HID_);
    float s1 = 0.f, s2 = 0.f;
    #pragma unroll 8
    for (int d = 0; d < 32; d++) {
        float4 gv = gr[d], a = as4[d], bq = ad4[d];
        s1 += gv.x*a.x + gv.y*a.y + gv.z*a.z + gv.w*a.w;
        s2 += gv.x*bq.x + gv.y*bq.y + gv.z*bq.z + gv.w*bq.w;
    }
    g_asrc[i] = s1;
    g_adst[i] = s2;
}

// pass 1: segment max of leaky_relu(a_src[s]+a_dst[t]) over dst (edges + self loops)
__global__ void k_e1(const int* __restrict__ src, const int* __restrict__ dst) {
    int idx = blockIdx.x * blockDim.x + threadIdx.x;
    if (idx >= EP_) return;
    int s, t;
    if (idx < E_) { s = src[idx]; t = dst[idx]; } else { s = t = idx - E_; }
    #pragma unroll
    for (int h = 0; h < H_; h++) {
        float ev = g_asrc[s*H_+h] + g_adst[t*H_+h];
        ev = ev > 0.f ? ev : 0.2f * ev;
        atomicMax(&g_emaxu[t*H_+h], fenc(ev));
    }
}

__global__ void k_decode_max() {
    int i = blockIdx.x * blockDim.x + threadIdx.x;
    if (i < N_*H_) g_emax[i] = fdec(g_emaxu[i]);
}

// pass 2: ex = exp(e - emax[dst]); den[dst] += ex
__global__ void k_e2(const int* __restrict__ src, const int* __restrict__ dst) {
    int idx = blockIdx.x * blockDim.x + threadIdx.x;
    if (idx >= EP_) return;
    int s, t;
    if (idx < E_) { s = src[idx]; t = dst[idx]; } else { s = t = idx - E_; }
    #pragma unroll
    for (int h = 0; h < H_; h++) {
        float ev = g_asrc[s*H_+h] + g_adst[t*H_+h];
        ev = ev > 0.f ? ev : 0.2f * ev;
        float x = __expf(ev - g_emax[t*H_+h]);
        g_ex[(size_t)idx*H_ + h] = x;
        atomicAdd(&g_den[t*H_+h], x);
    }
}

// den -> 0.25/den (folds the head mean)
__global__ void k_wden() {
    int i = blockIdx.x * blockDim.x + threadIdx.x;
    if (i < N_*H_) g_den[i] = 0.25f / g_den[i];
}

// GAT self-loop contribution, direct write
__global__ void k_agg_self() {
    int idx = blockIdx.x * blockDim.x + threadIdx.x;
    if (idx >= N_*32) return;
    int node = idx >> 5, lane = idx & 31;
    float w0 = g_ex[(size_t)(E_+node)*H_+0] * g_den[node*H_+0];
    float w1 = g_ex[(size_t)(E_+node)*H_+1] * g_den[node*H_+1];
    float w2 = g_ex[(size_t)(E_+node)*H_+2] * g_den[node*H_+2];
    float w3 = g_ex[(size_t)(E_+node)*H_+3] * g_den[node*H_+3];
    const float4* gb = (const float4*)(g_gbuf + (size_t)node*H_*HID_);
    float4 v0 = gb[lane], v1 = gb[32+lane], v2 = gb[64+lane], v3 = gb[96+lane];
    float4 m;
    m.x = w0*v0.x + w1*v1.x + w2*v2.x + w3*v3.x;
    m.y = w0*v0.y + w1*v1.y + w2*v2.y + w3*v3.y;
    m.z = w0*v0.z + w1*v1.z + w2*v2.z + w3*v3.z;
    m.w = w0*v0.w + w1*v1.w + w2*v2.w + w3*v3.w;
    ((float4*)(g_agg + (size_t)node*HID_))[lane] = m;
}

// GAT edge scatter: warp per edge, fused head-weighted sum + float4 atomics
__global__ void k_gat_scatter(const int* __restrict__ src, const int* __restrict__ dst) {
    int gi = blockIdx.x * blockDim.x + threadIdx.x;
    int e = gi >> 5, lane = gi & 31;
    if (e >= E_) return;
    int s = src[e], t = dst[e];
    float w0 = g_ex[(size_t)e*H_+0] * g_den[t*H_+0];
    float w1 = g_ex[(size_t)e*H_+1] * g_den[t*H_+1];
    float w2 = g_ex[(size_t)e*H_+2] * g_den[t*H_+2];
    float w3 = g_ex[(size_t)e*H_+3] * g_den[t*H_+3];
    const float4* gb = (const float4*)(g_gbuf + (size_t)s*H_*HID_);
    float4 v0 = gb[lane], v1 = gb[32+lane], v2 = gb[64+lane], v3 = gb[96+lane];
    float4 m;
    m.x = w0*v0.x + w1*v1.x + w2*v2.x + w3*v3.x;
    m.y = w0*v0.y + w1*v1.y + w2*v2.y + w3*v3.y;
    m.z = w0*v0.z + w1*v1.z + w2*v2.z + w3*v3.z;
    m.w = w0*v0.w + w1*v1.w + w2*v2.w + w3*v3.w;
    atomicAdd(((float4*)(g_agg + (size_t)t*HID_)) + lane, m);
}

__global__ void k_reparam(const float* __restrict__ eps) {
    int i = blockIdx.x * blockDim.x + threadIdx.x;
    if (i >= N_*Z_) return;
    float lv = g_lv[i];
    lv = fminf(10.0f, fmaxf(-10.0f, lv));
    g_zb[i] = g_mu[i] + eps[i] * expf(0.5f * lv);
}

__global__ void k_copyout(float* __restrict__ omu, float* __restrict__ olv) {
    int i = blockIdx.x * blockDim.x + threadIdx.x;
    if (i >= N_*Z_) return;
    omu[i] = g_mu[i];
    olv[i] = g_lv[i];
}

// ---------------- generic SGEMM: C[M,Nc] = A[M,K] @ B[K,Nc]  (+bias,+resid,relu) ----
// BM=BN=64, BK=16, 128 threads, 4x8 micro-tile. Nc must be a multiple of 64,
// K a multiple of 16 (true for all call sites: Nc in {64,128,512}, K in {64,128}).
__global__ __launch_bounds__(128) void sgemm(
    const float* __restrict__ A, const float* __restrict__ B, float* __restrict__ C,
    int M, int Nc, int K,
    const float* __restrict__ bias, const float* __restrict__ resid, int relu)
{
    __shared__ float As[64][20];   // [m][k], padded row (80B, 16B aligned)
    __shared__ float Bs[16][64];
    int tid = threadIdx.x;
    int tx = tid & 7, ty = tid >> 3;          // 8 col-groups x 16 row-groups
    int rb = blockIdx.y * 64, cb = blockIdx.x * 64;

    float acc[4][8];
    #pragma unroll
    for (int i = 0; i < 4; i++)
        #pragma unroll
        for (int j = 0; j < 8; j++) acc[i][j] = 0.f;

    for (int kk = 0; kk < K; kk += 16) {
        __syncthreads();
        #pragma unroll
        for (int u = 0; u < 2; u++) {
            int f = tid + 128*u;              // 0..255
            int r  = f >> 2, kq = (f & 3) * 4;
            float4 va = make_float4(0.f, 0.f, 0.f, 0.f);
            if (rb + r < M) va = *(const float4*)(A + (size_t)(rb + r)*K + kk + kq);
            *(float4*)&As[r][kq] = va;
            int kr = f >> 4, cq = (f & 15) * 4;
            float4 vb = *(const float4*)(B + (size_t)(kk + kr)*Nc + cb + cq);
            *(float4*)&Bs[kr][cq] = vb;
        }
        __syncthreads();
        #pragma unroll
        for (int k = 0; k < 16; k++) {
            float aa[4];
            #pragma unroll
            for (int i = 0; i < 4; i++) aa[i] = As[ty*4 + i][k];
            float4 b0 = *(float4*)&Bs[k][tx*8];
            float4 b1 = *(float4*)&Bs[k][tx*8 + 4];
            float bb[8] = {b0.x, b0.y, b0.z, b0.w, b1.x, b1.y, b1.z, b1.w};
            #pragma unroll
            for (int i = 0; i < 4; i++)
                #pragma unroll
                for (int j = 0; j < 8; j++)
                    acc[i][j] = fmaf(aa[i], bb[j], acc[i][j]);
        }
    }

    #pragma unroll
    for (int i = 0; i < 4; i++) {
        int r = rb + ty*4 + i;
        if (r >= M) continue;
        int c0 = cb + tx*8;
        float* Cp = C + (size_t)r*Nc + c0;
        const float* rp = resid ? resid + (size_t)r*Nc + c0 : nullptr;
        #pragma unroll
        for (int j = 0; j < 8; j++) {
            float v = acc[i][j];
            if (bias) v += bias[c0 + j];
            if (rp)   v += rp[j];
            if (relu) v = fmaxf(v, 0.f);
            Cp[j] = v;
        }
    }
}

// ---------------- logits SYRK: C[N,N] = D @ D^T, D = [N, 64] ----------------------
// 128x128 block tile, K=64 in two 32-chunks, 256 threads, 8x8 micro-tile.
// Symmetry: only by <= bx computed; mirror tile stored via register transpose.
__global__ __launch_bounds__(256, 2) void syrk(const float* __restrict__ D,
                                               float* __restrict__ C)
{
    int bx = blockIdx.x, by = blockIdx.y;
    if (by > bx) return;
    __shared__ float As[32][132];
    __shared__ float Bs[32][132];
    int tid = threadIdx.x;
    int tx = tid & 15, ty = tid >> 4;
    int rowBase = bx * 128, colBase = by * 128;

    float acc[8][8];
    #pragma unroll
    for (int i = 0; i < 8; i++)
        #pragma unroll
        for (int j = 0; j < 8; j++) acc[i][j] = 0.f;

    for (int kk = 0; kk < 64; kk += 32) {
        __syncthreads();
        #pragma unroll
        for (int u = 0; u < 4; u++) {
            int f = tid + 256*u;                 // 0..1023
            int r = f >> 3, kq = (f & 7) * 4;
            float4 va = make_float4(0.f, 0.f, 0.f, 0.f), vb = va;
            int ra = rowBase + r;
            if (ra < N_) va = *(const float4*)(D + (size_t)ra*Z_ + kk + kq);
            int rc = colBase + r;
            if (rc < N_) vb = *(const float4*)(D + (size_t)rc*Z_ + kk + kq);
            As[kq+0][r] = va.x; As[kq+1][r] = va.y; As[kq+2][r] = va.z; As[kq+3][r] = va.w;
            Bs[kq+0][r] = vb.x; Bs[kq+1][r] = vb.y; Bs[kq+2][r] = vb.z; Bs[kq+3][r] = vb.w;
        }
        __syncthreads();
        #pragma unroll
        for (int k = 0; k < 32; k++) {
            float4 a0 = *(float4*)&As[k][ty*8];
            float4 a1 = *(float4*)&As[k][ty*8 + 4];
            float4 b0 = *(float4*)&Bs[k][tx*8];
            float4 b1 = *(float4*)&Bs[k][tx*8 + 4];
            float aa[8] = {a0.x, a0.y, a0.z, a0.w, a1.x, a1.y, a1.z, a1.w};
            float bb[8] = {b0.x, b0.y, b0.z, b0.w, b1.x, b1.y, b1.z, b1.w};
            #pragma unroll
            for (int i = 0; i < 8; i++)
                #pragma unroll
                for (int j = 0; j < 8; j++)
                    acc[i][j] = fmaf(aa[i], bb[j], acc[i][j]);
        }
    }

    // direct tile store
    bool fullCols = (colBase + 127 < N_);
    #pragma unroll
    for (int i = 0; i < 8; i++) {
        int r = rowBase + ty*8 + i;
        if (r >= N_) continue;
        float* Cp = C + (size_t)r*N_ + colBase + tx*8;
        if (fullCols) {
            float4 s0 = make_float4(acc[i][0], acc[i][1], acc[i][2], acc[i][3]);
            float4 s1 = make_float4(acc[i][4], acc[i][5], acc[i][6], acc[i][7]);
            *(float4*)Cp = s0;
            *(float4*)(Cp + 4) = s1;
        } else {
            #pragma unroll
            for (int j = 0; j < 8; j++)
                if (colBase + tx*8 + j < N_) Cp[j] = acc[i][j];
        }
    }

    // mirror tile store (register transpose)
    if (bx != by) {
        #pragma unroll
        for (int j = 0; j < 8; j++) {
            int r2 = colBase + tx*8 + j;
            if (r2 >= N_) continue;
            int c2 = rowBase + ty*8;
            float* Cp = C + (size_t)r2*N_ + c2;
            if (c2 + 7 < N_) {
                float4 t0 = make_float4(acc[0][j], acc[1][j], acc[2][j], acc[3][j]);
                float4 t1 = make_float4(acc[4][j], acc[5][j], acc[6][j], acc[7][j]);
                *(float4*)Cp = t0;
                *(float4*)(Cp + 4) = t1;
            } else {
                #pragma unroll
                for (int i = 0; i < 8; i++)
                    if (c2 + i < N_) Cp[i] = acc[i][j];
            }
        }
    }
}

// ---------------- launch ----------------
static inline int cdiv(int a, int b) { return (a + b - 1) / b; }

extern "C" void kernel_launch(void* const* d_in, const int* in_sizes, int n_in,
                              void* d_out, int out_size) {
    (void)in_sizes; (void)n_in;
    const float* x     = (const float*)d_in[0];
    const int*   ei    = (const int*)  d_in[1];
    const float* eps   = (const float*)d_in[2];
    const float* gcn_w = (const float*)d_in[3];
    const float* gcn_b = (const float*)d_in[4];
    const float* gat_w = (const float*)d_in[5];
    const float* att_s = (const float*)d_in[6];
    const float* att_d = (const float*)d_in[7];
    const float* gat_b = (const float*)d_in[8];
    const float* w1    = (const float*)d_in[9];
    const float* b1    = (const float*)d_in[10];
    const float* w2    = (const float*)d_in[11];
    const float* b2    = (const float*)d_in[12];
    const float* mu_w  = (const float*)d_in[13];
    const float* mu_b  = (const float*)d_in[14];
    const float* lv_w  = (const float*)d_in[15];
    const float* lv_b  = (const float*)d_in[16];
    const float* dw1   = (const float*)d_in[17];
    const float* db1   = (const float*)d_in[18];
    const float* dw2   = (const float*)d_in[19];
    const float* db2   = (const float*)d_in[20];
    const int* srcp = ei;
    const int* dstp = ei + E_;
    float* out = (float*)d_out;

    float *ph0, *pacc, *ph1, *pg, *ph2, *ph3, *ph4, *pmu, *plv, *pz, *pd1, *pd;
    cudaGetSymbolAddress((void**)&ph0,  g_h0);
    cudaGetSymbolAddress((void**)&pacc, g_acc);
    cudaGetSymbolAddress((void**)&ph1,  g_h1);
    cudaGetSymbolAddress((void**)&pg,   g_gbuf);
    cudaGetSymbolAddress((void**)&ph2,  g_h2);
    cudaGetSymbolAddress((void**)&ph3,  g_h3);
    cudaGetSymbolAddress((void**)&ph4,  g_h4);
    cudaGetSymbolAddress((void**)&pmu,  g_mu);
    cudaGetSymbolAddress((void**)&plv,  g_lv);
    cudaGetSymbolAddress((void**)&pz,   g_zb);
    cudaGetSymbolAddress((void**)&pd1,  g_d1);
    cudaGetSymbolAddress((void**)&pd,   g_db);

    const int T = 256;

    // ---- GCN ----
    k_init<<<cdiv(N_*H_, T), T>>>();
    k_deg <<<cdiv(E_, T), T>>>(dstp);
    k_dinv<<<cdiv(N_, T), T>>>();
    sgemm<<<dim3(HID_/64, cdiv(N_, 64)), 128>>>(x, gcn_w, ph0, N_, HID_, 128,
                                                nullptr, nullptr, 0);
    k_gcn_self   <<<cdiv(N_*32, T), T>>>();
    k_gcn_scatter<<<cdiv(E_*32, T), T>>>(srcp, dstp);
    k_bias_relu  <<<cdiv(N_*HID_, T), T>>>(pacc, ph1, gcn_b, N_*HID_, HID_-1);

    // ---- GAT ----
    sgemm<<<dim3(H_*HID_/64, cdiv(N_, 64)), 128>>>(ph1, gat_w, pg, N_, H_*HID_, 128,
                                                   nullptr, nullptr, 0);
    k_att<<<cdiv(N_*H_, T), T>>>(att_s, att_d);
    k_e1 <<<cdiv(EP_, T), T>>>(srcp, dstp);
    k_decode_max<<<cdiv(N_*H_, T), T>>>();
    k_e2 <<<cdiv(EP_, T), T>>>(srcp, dstp);
    k_wden<<<cdiv(N_*H_, T), T>>>();
    k_agg_self   <<<cdiv(N_*32, T), T>>>();
    k_gat_scatter<<<cdiv(E_*32, T), T>>>(srcp, dstp);
    k_bias_relu  <<<cdiv(N_*HID_, T), T>>>( // h2 = relu(agg + gat_b)
        (const float*)nullptr == nullptr ? (float*)nullptr : nullptr, nullptr, nullptr, 0, 0);
    // (the line above is replaced by the real launch below; keep the real one)
    {
        float* paggp; cudaGetSymbolAddress((void**)&paggp, g_agg);
        k_bias_relu<<<cdiv(N_*HID_, T), T>>>(paggp, ph2, gat_b, N_*HID_, HID_-1);
    }

    // ---- encoder MLP ----
    sgemm<<<dim3(2, cdiv(N_, 64)), 128>>>(ph2, w1, ph3, N_, HID_, 128, b1, nullptr, 1);
    sgemm<<<dim3(2, cdiv(N_, 64)), 128>>>(ph3, w2, ph4, N_, HID_, 128, b2, nullptr, 1);
    sgemm<<<dim3(1, cdiv(N_, 64)), 128>>>(ph4, mu_w, pmu, N_, Z_, 128, mu_b, nullptr, 0);
    sgemm<<<dim3(1, cdiv(N_, 64)), 128>>>(ph4, lv_w, plv, N_, Z_, 128, lv_b, nullptr, 0);

    // ---- reparameterize + outputs mu/logvar ----
    k_reparam<<<cdiv(N_*Z_, T), T>>>(eps);
    if ((size_t)out_size >= (size_t)N_*N_ + 2u*N_*Z_) {
        k_copyout<<<cdiv(N_*Z_, T), T>>>(out + (size_t)N_*N_,
                                         out + (size_t)N_*N_ + (size_t)N_*Z_);
    }

    // ---- decoder ----
    sgemm<<<dim3(2, cdiv(N_, 64)), 128>>>(pz, dw1, pd1, N_, HID_, 64, db1, nullptr, 1);
    sgemm<<<dim3(1, cdiv(N_, 64)), 128>>>(pd1, dw2, pd, N_, Z_, 128, db2, pz, 0);

    // ---- logits = d @ d^T (symmetric) ----
    syrk<<<dim3(cdiv(N_, 128), cdiv(N_, 128)), 256>>>(pd, out);
}

// round 6
// speedup vs baseline: 1.0805x; 1.0805x over previous
#include <cuda_runtime.h>
#include <mma.h>
#include <cstdint>
#include <cstddef>

using namespace nvcuda;

#define N_   10000
#define E_   320000
#define HID_ 128
#define Z_   64
#define H_   4
#define EP_  (E_ + N_)

// ---------------- scratch (device globals; no allocation allowed) ----------------
__device__ float    g_h0 [N_*HID_];      // x @ gcn_w
__device__ float    g_acc[N_*HID_];      // GCN aggregation
__device__ float    g_h1 [N_*HID_];      // relu(acc + gcn_b)
__device__ float    g_gbuf[N_*H_*HID_];  // h1 @ gat_w   [n, h*128+d]
__device__ float    g_asrc[N_*H_];
__device__ float    g_adst[N_*H_];
__device__ unsigned g_emaxu[N_*H_];
__device__ float    g_emax[N_*H_];
__device__ float    g_den[N_*H_];        // later holds 0.25/den
__device__ float    g_ex [EP_*H_];       // self loop edge i stored at (E_+i)
__device__ float    g_agg[N_*HID_];
__device__ float    g_h2 [N_*HID_];
__device__ float    g_h3 [N_*HID_];
__device__ float    g_h4 [N_*HID_];
__device__ float    g_mu [N_*Z_];
__device__ float    g_lv [N_*Z_];
__device__ float    g_zb [N_*Z_];
__device__ float    g_d1 [N_*HID_];
__device__ float    g_db [N_*Z_];
__device__ float    g_deg [N_];
__device__ float    g_dinv[N_];

// ---------------- helpers ----------------
__device__ __forceinline__ unsigned fenc(float f) {
    unsigned u = __float_as_uint(f);
    return (u & 0x80000000u) ? ~u : (u | 0x80000000u);
}
__device__ __forceinline__ float fdec(unsigned x) {
    unsigned u = (x & 0x80000000u) ? (x ^ 0x80000000u) : ~x;
    return __uint_as_float(u);
}
__device__ __forceinline__ float to_tf32(float x) {
    float r;
    asm("cvt.rna.tf32.f32 %0, %1;" : "=f"(r) : "f"(x));
    return r;
}

// ---------------- init: deg=1 (self loop), emax=enc(-FLT_MAX), den=0 --------------
__global__ void k_init() {
    int i = blockIdx.x * blockDim.x + threadIdx.x;
    if (i < N_) g_deg[i] = 1.0f;
    if (i < N_*H_) { g_emaxu[i] = 0x00800000u; g_den[i] = 0.0f; }
}

__global__ void k_deg(const int* __restrict__ dst) {
    int e = blockIdx.x * blockDim.x + threadIdx.x;
    if (e < E_) atomicAdd(&g_deg[dst[e]], 1.0f);
}

__global__ void k_dinv() {
    int i = blockIdx.x * blockDim.x + threadIdx.x;
    if (i < N_) g_dinv[i] = rsqrtf(g_deg[i]);
}

// GCN self-loop contribution, direct write (no atomics)
__global__ void k_gcn_self() {
    int idx = blockIdx.x * blockDim.x + threadIdx.x;
    if (idx >= N_*32) return;
    int node = idx >> 5, lane = idx & 31;
    float c = g_dinv[node]; c = c * c;
    float4 v = ((const float4*)(g_h0 + (size_t)node*HID_))[lane];
    v.x *= c; v.y *= c; v.z *= c; v.w *= c;
    ((float4*)(g_acc + (size_t)node*HID_))[lane] = v;
}

// GCN edge scatter: warp per edge, float4 vector atomics (sm_90+)
__global__ void k_gcn_scatter(const int* __restrict__ src, const int* __restrict__ dst) {
    int gi = blockIdx.x * blockDim.x + threadIdx.x;
    int e = gi >> 5, lane = gi & 31;
    if (e >= E_) return;
    int s = src[e], t = dst[e];
    float c = g_dinv[s] * g_dinv[t];
    float4 v = ((const float4*)(g_h0 + (size_t)s*HID_))[lane];
    v.x *= c; v.y *= c; v.z *= c; v.w *= c;
    atomicAdd(((float4*)(g_acc + (size_t)t*HID_)) + lane, v);
}

__global__ void k_bias_relu(const float* __restrict__ in, float* __restrict__ out,
                            const float* __restrict__ b, int total, int cmask) {
    int i = blockIdx.x * blockDim.x + threadIdx.x;
    if (i >= total) return;
    float v = in[i] + b[i & cmask];
    out[i] = fmaxf(v, 0.0f);
}

// attention logits per (node, head)
__global__ void k_att(const float* __restrict__ att_s, const float* __restrict__ att_d) {
    int i = blockIdx.x * blockDim.x + threadIdx.x;
    if (i >= N_*H_) return;
    int h = i & (H_-1);
    const float4* gr  = (const float4*)(g_gbuf + (size_t)i*HID_);
    const float4* as4 = (const float4*)(att_s + h*HID_);
    const float4* ad4 = (const float4*)(att_d + h*HID_);
    float s1 = 0.f, s2 = 0.f;
    #pragma unroll 8
    for (int d = 0; d < 32; d++) {
        float4 gv = gr[d], a = as4[d], bq = ad4[d];
        s1 += gv.x*a.x + gv.y*a.y + gv.z*a.z + gv.w*a.w;
        s2 += gv.x*bq.x + gv.y*bq.y + gv.z*bq.z + gv.w*bq.w;
    }
    g_asrc[i] = s1;
    g_adst[i] = s2;
}

// pass 1: segment max of leaky_relu(a_src[s]+a_dst[t]) over dst (edges + self loops)
__global__ void k_e1(const int* __restrict__ src, const int* __restrict__ dst) {
    int idx = blockIdx.x * blockDim.x + threadIdx.x;
    if (idx >= EP_) return;
    int s, t;
    if (idx < E_) { s = src[idx]; t = dst[idx]; } else { s = t = idx - E_; }
    #pragma unroll
    for (int h = 0; h < H_; h++) {
        float ev = g_asrc[s*H_+h] + g_adst[t*H_+h];
        ev = ev > 0.f ? ev : 0.2f * ev;
        atomicMax(&g_emaxu[t*H_+h], fenc(ev));
    }
}

__global__ void k_decode_max() {
    int i = blockIdx.x * blockDim.x + threadIdx.x;
    if (i < N_*H_) g_emax[i] = fdec(g_emaxu[i]);
}

// pass 2: ex = exp(e - emax[dst]); den[dst] += ex
__global__ void k_e2(const int* __restrict__ src, const int* __restrict__ dst) {
    int idx = blockIdx.x * blockDim.x + threadIdx.x;
    if (idx >= EP_) return;
    int s, t;
    if (idx < E_) { s = src[idx]; t = dst[idx]; } else { s = t = idx - E_; }
    #pragma unroll
    for (int h = 0; h < H_; h++) {
        float ev = g_asrc[s*H_+h] + g_adst[t*H_+h];
        ev = ev > 0.f ? ev : 0.2f * ev;
        float xv = __expf(ev - g_emax[t*H_+h]);
        g_ex[(size_t)idx*H_ + h] = xv;
        atomicAdd(&g_den[t*H_+h], xv);
    }
}

// den -> 0.25/den (folds the head mean)
__global__ void k_wden() {
    int i = blockIdx.x * blockDim.x + threadIdx.x;
    if (i < N_*H_) g_den[i] = 0.25f / g_den[i];
}

// GAT self-loop contribution, direct write
__global__ void k_agg_self() {
    int idx = blockIdx.x * blockDim.x + threadIdx.x;
    if (idx >= N_*32) return;
    int node = idx >> 5, lane = idx & 31;
    float w0 = g_ex[(size_t)(E_+node)*H_+0] * g_den[node*H_+0];
    float w1 = g_ex[(size_t)(E_+node)*H_+1] * g_den[node*H_+1];
    float w2 = g_ex[(size_t)(E_+node)*H_+2] * g_den[node*H_+2];
    float w3 = g_ex[(size_t)(E_+node)*H_+3] * g_den[node*H_+3];
    const float4* gb = (const float4*)(g_gbuf + (size_t)node*H_*HID_);
    float4 v0 = gb[lane], v1 = gb[32+lane], v2 = gb[64+lane], v3 = gb[96+lane];
    float4 m;
    m.x = w0*v0.x + w1*v1.x + w2*v2.x + w3*v3.x;
    m.y = w0*v0.y + w1*v1.y + w2*v2.y + w3*v3.y;
    m.z = w0*v0.z + w1*v1.z + w2*v2.z + w3*v3.z;
    m.w = w0*v0.w + w1*v1.w + w2*v2.w + w3*v3.w;
    ((float4*)(g_agg + (size_t)node*HID_))[lane] = m;
}

// GAT edge scatter: warp per edge, fused head-weighted sum + float4 atomics
__global__ void k_gat_scatter(const int* __restrict__ src, const int* __restrict__ dst) {
    int gi = blockIdx.x * blockDim.x + threadIdx.x;
    int e = gi >> 5, lane = gi & 31;
    if (e >= E_) return;
    int s = src[e], t = dst[e];
    float w0 = g_ex[(size_t)e*H_+0] * g_den[t*H_+0];
    float w1 = g_ex[(size_t)e*H_+1] * g_den[t*H_+1];
    float w2 = g_ex[(size_t)e*H_+2] * g_den[t*H_+2];
    float w3 = g_ex[(size_t)e*H_+3] * g_den[t*H_+3];
    const float4* gb = (const float4*)(g_gbuf + (size_t)s*H_*HID_);
    float4 v0 = gb[lane], v1 = gb[32+lane], v2 = gb[64+lane], v3 = gb[96+lane];
    float4 m;
    m.x = w0*v0.x + w1*v1.x + w2*v2.x + w3*v3.x;
    m.y = w0*v0.y + w1*v1.y + w2*v2.y + w3*v3.y;
    m.z = w0*v0.z + w1*v1.z + w2*v2.z + w3*v3.z;
    m.w = w0*v0.w + w1*v1.w + w2*v2.w + w3*v3.w;
    atomicAdd(((float4*)(g_agg + (size_t)t*HID_)) + lane, m);
}

// reparameterize + copy mu/logvar to output (fused)
__global__ void k_reparam(const float* __restrict__ eps,
                          float* __restrict__ omu, float* __restrict__ olv, int wr) {
    int i = blockIdx.x * blockDim.x + threadIdx.x;
    if (i >= N_*Z_) return;
    float lv = g_lv[i];
    float mu = g_mu[i];
    float lvc = fminf(10.0f, fmaxf(-10.0f, lv));
    g_zb[i] = mu + eps[i] * expf(0.5f * lvc);
    if (wr) { omu[i] = mu; olv[i] = lv; }
}

// ---------------- generic SGEMM: C[M,Nc] = A[M,K] @ B[K,Nc]  (+bias,+resid,relu) ----
// BM=BN=64, BK=32, 256 threads, 4x4 micro-tile. Nc multiple of 64, K multiple of 32.
__global__ __launch_bounds__(256) void sgemm(
    const float* __restrict__ A, const float* __restrict__ B, float* __restrict__ C,
    int M, int Nc, int K,
    const float* __restrict__ bias, const float* __restrict__ resid, int relu)
{
    __shared__ float As[32][68];   // [k][m]
    __shared__ float Bs[32][68];   // [k][n]
    int tid = threadIdx.x;
    int tx = tid & 15, ty = tid >> 4;        // 16 x 16 threads, 4x4 outputs each
    int rb = blockIdx.y * 64, cb = blockIdx.x * 64;

    float acc[4][4];
    #pragma unroll
    for (int i = 0; i < 4; i++)
        #pragma unroll
        for (int j = 0; j < 4; j++) acc[i][j] = 0.f;

    for (int kk = 0; kk < K; kk += 32) {
        __syncthreads();
        #pragma unroll
        for (int u = 0; u < 2; u++) {
            int f = tid + 256*u;             // 0..511
            int r  = f >> 3, kq = (f & 7) * 4;   // A: row r (0..63), k kq..kq+3
            float4 va = make_float4(0.f, 0.f, 0.f, 0.f);
            if (rb + r < M) va = *(const float4*)(A + (size_t)(rb + r)*K + kk + kq);
            As[kq+0][r] = va.x; As[kq+1][r] = va.y; As[kq+2][r] = va.z; As[kq+3][r] = va.w;
            int kr = f >> 4, cq = (f & 15) * 4;  // B: k row kr (0..31), col cq..cq+3
            float4 vb = *(const float4*)(B + (size_t)(kk + kr)*Nc + cb + cq);
            *(float4*)&Bs[kr][cq] = vb;
        }
        __syncthreads();
        #pragma unroll
        for (int k = 0; k < 32; k++) {
            float4 a = *(float4*)&As[k][ty*4];
            float4 b = *(float4*)&Bs[k][tx*4];
            float aa[4] = {a.x, a.y, a.z, a.w};
            float bb[4] = {b.x, b.y, b.z, b.w};
            #pragma unroll
            for (int i = 0; i < 4; i++)
                #pragma unroll
                for (int j = 0; j < 4; j++)
                    acc[i][j] = fmaf(aa[i], bb[j], acc[i][j]);
        }
    }

    int c0 = cb + tx*4;
    #pragma unroll
    for (int i = 0; i < 4; i++) {
        int r = rb + ty*4 + i;
        if (r >= M) continue;
        float v[4];
        #pragma unroll
        for (int j = 0; j < 4; j++) {
            v[j] = acc[i][j];
            if (bias)  v[j] += bias[c0 + j];
            if (resid) v[j] += resid[(size_t)r*Nc + c0 + j];
            if (relu)  v[j] = fmaxf(v[j], 0.f);
        }
        *(float4*)(C + (size_t)r*Nc + c0) = make_float4(v[0], v[1], v[2], v[3]);
    }
}

// ---------------- logits SYRK (TF32 tensor cores, 3-term split) -------------------
// C[N,N] = D @ D^T, D = [N, 64] fp32. Split D = Dh + Dl (tf32 Dekker split):
//   C = Dh·Dh^T + Dh·Dl^T + Dl·Dh^T   (error ~2^-22, fp32-class)
// CTA: 128x128 tile, 256 thr = 8 warps (4x2), warp tile 32x64 = 2x4 wmma m16n16k8.
// Symmetry: by <= bx only; mirror tile stored via store_matrix_sync(col_major).
__global__ __launch_bounds__(256, 2) void syrk_tf32(const float* __restrict__ D,
                                                    float* __restrict__ C)
{
    int bx = blockIdx.x, by = blockIdx.y;
    if (by > bx) return;

    __shared__ float sAh[128][20], sAl[128][20];
    __shared__ float sBh[128][20], sBl[128][20];
    __shared__ float sStage[8][16][16];

    int tid = threadIdx.x;
    int wid = tid >> 5;
    int lane = tid & 31;
    int warp_m = wid & 3, warp_n = wid >> 2;
    int rowBase = bx * 128, colBase = by * 128;

    wmma::fragment<wmma::accumulator, 16, 16, 8, float> acc[2][4];
    #pragma unroll
    for (int i = 0; i < 2; i++)
        #pragma unroll
        for (int j = 0; j < 4; j++) wmma::fill_fragment(acc[i][j], 0.0f);

    for (int kk = 0; kk < 64; kk += 16) {
        __syncthreads();
        #pragma unroll
        for (int u = 0; u < 2; u++) {
            int f = tid + 256*u;               // 0..511
            int r = f >> 2, kq = (f & 3) * 4;  // r 0..127, kq 0,4,8,12
            // A side (rows of this block-row)
            int ra = rowBase + r;
            float4 v = make_float4(0.f, 0.f, 0.f, 0.f);
            if (ra < N_) v = *(const float4*)(D + (size_t)ra*Z_ + kk + kq);
            float hx = to_tf32(v.x), hy = to_tf32(v.y), hz = to_tf32(v.z), hw = to_tf32(v.w);
            *(float4*)&sAh[r][kq] = make_float4(hx, hy, hz, hw);
            *(float4*)&sAl[r][kq] = make_float4(to_tf32(v.x - hx), to_tf32(v.y - hy),
                                                to_tf32(v.z - hz), to_tf32(v.w - hw));
            // B side (rows of the block-col)
            int rc = colBase + r;
            float4 w = make_float4(0.f, 0.f, 0.f, 0.f);
            if (rc < N_) w = *(const float4*)(D + (size_t)rc*Z_ + kk + kq);
            float gx = to_tf32(w.x), gy = to_tf32(w.y), gz = to_tf32(w.z), gw = to_tf32(w.w);
            *(float4*)&sBh[r][kq] = make_float4(gx, gy, gz, gw);
            *(float4*)&sBl[r][kq] = make_float4(to_tf32(w.x - gx), to_tf32(w.y - gy),
                                                to_tf32(w.z - gz), to_tf32(w.w - gw));
        }
        __syncthreads();

        #pragma unroll
        for (int ks = 0; ks < 16; ks += 8) {
            wmma::fragment<wmma::matrix_a, 16, 16, 8, wmma::precision::tf32, wmma::row_major> ah[2], al[2];
            #pragma unroll
            for (int i = 0; i < 2; i++) {
                const float* p = &sAh[warp_m*32 + i*16][ks];
                wmma::load_matrix_sync(ah[i], p, 20);
                const float* q = &sAl[warp_m*32 + i*16][ks];
                wmma::load_matrix_sync(al[i], q, 20);
            }
            #pragma unroll
            for (int j = 0; j < 4; j++) {
                wmma::fragment<wmma::matrix_b, 16, 16, 8, wmma::precision::tf32, wmma::col_major> bh, bl;
                wmma::load_matrix_sync(bh, &sBh[warp_n*64 + j*16][ks], 20);
                wmma::load_matrix_sync(bl, &sBl[warp_n*64 + j*16][ks], 20);
                #pragma unroll
                for (int i = 0; i < 2; i++) {
                    wmma::mma_sync(acc[i][j], ah[i], bh, acc[i][j]);
                    wmma::mma_sync(acc[i][j], ah[i], bl, acc[i][j]);
                    wmma::mma_sync(acc[i][j], al[i], bh, acc[i][j]);
                }
            }
        }
    }

    bool guard = (rowBase + 128 > N_);   // only bx==78 tiles touch the ragged edge
    if (!guard) {
        #pragma unroll
        for (int i = 0; i < 2; i++)
            #pragma unroll
            for (int j = 0; j < 4; j++) {
                int R0 = rowBase + warp_m*32 + i*16;
                int C0 = colBase + warp_n*64 + j*16;
                wmma::store_matrix_sync(C + (size_t)R0*N_ + C0, acc[i][j], N_,
                                        wmma::mem_row_major);
                if (bx != by)
                    wmma::store_matrix_sync(C + (size_t)C0*N_ + R0, acc[i][j], N_,
                                            wmma::mem_col_major);
            }
    } else {
        __syncthreads();   // smem operands no longer needed; reuse stage buffer safely
        #pragma unroll
        for (int i = 0; i < 2; i++)
            #pragma unroll
            for (int j = 0; j < 4; j++) {
                wmma::store_matrix_sync(&sStage[wid][0][0], acc[i][j], 16,
                                        wmma::mem_row_major);
                __syncwarp();
                int R0 = rowBase + warp_m*32 + i*16;
                int C0 = colBase + warp_n*64 + j*16;
                #pragma unroll
                for (int e = 0; e < 8; e++) {
                    int idx = lane + e*32;
                    int r = idx >> 4, c = idx & 15;
                    int R = R0 + r, Cc = C0 + c;
                    if (R < N_ && Cc < N_) {
                        float v = sStage[wid][r][c];
                        C[(size_t)R*N_ + Cc] = v;
                        if (bx != by) C[(size_t)Cc*N_ + R] = v;
                    }
                }
                __syncwarp();
            }
    }
}

// ---------------- launch ----------------
static inline int cdiv(int a, int b) { return (a + b - 1) / b; }

extern "C" void kernel_launch(void* const* d_in, const int* in_sizes, int n_in,
                              void* d_out, int out_size) {
    (void)in_sizes; (void)n_in;
    const float* x     = (const float*)d_in[0];
    const int*   ei    = (const int*)  d_in[1];
    const float* eps   = (const float*)d_in[2];
    const float* gcn_w = (const float*)d_in[3];
    const float* gcn_b = (const float*)d_in[4];
    const float* gat_w = (const float*)d_in[5];
    const float* att_s = (const float*)d_in[6];
    const float* att_d = (const float*)d_in[7];
    const float* gat_b = (const float*)d_in[8];
    const float* w1    = (const float*)d_in[9];
    const float* b1    = (const float*)d_in[10];
    const float* w2    = (const float*)d_in[11];
    const float* b2    = (const float*)d_in[12];
    const float* mu_w  = (const float*)d_in[13];
    const float* mu_b  = (const float*)d_in[14];
    const float* lv_w  = (const float*)d_in[15];
    const float* lv_b  = (const float*)d_in[16];
    const float* dw1   = (const float*)d_in[17];
    const float* db1   = (const float*)d_in[18];
    const float* dw2   = (const float*)d_in[19];
    const float* db2   = (const float*)d_in[20];
    const int* srcp = ei;
    const int* dstp = ei + E_;
    float* out = (float*)d_out;

    float *ph0, *pacc, *ph1, *pg, *pagg, *ph2, *ph3, *ph4, *pmu, *plv, *pz, *pd1, *pd;
    cudaGetSymbolAddress((void**)&ph0,  g_h0);
    cudaGetSymbolAddress((void**)&pacc, g_acc);
    cudaGetSymbolAddress((void**)&ph1,  g_h1);
    cudaGetSymbolAddress((void**)&pg,   g_gbuf);
    cudaGetSymbolAddress((void**)&pagg, g_agg);
    cudaGetSymbolAddress((void**)&ph2,  g_h2);
    cudaGetSymbolAddress((void**)&ph3,  g_h3);
    cudaGetSymbolAddress((void**)&ph4,  g_h4);
    cudaGetSymbolAddress((void**)&pmu,  g_mu);
    cudaGetSymbolAddress((void**)&plv,  g_lv);
    cudaGetSymbolAddress((void**)&pz,   g_zb);
    cudaGetSymbolAddress((void**)&pd1,  g_d1);
    cudaGetSymbolAddress((void**)&pd,   g_db);

    const int T = 256;

    // ---- GCN ----
    k_init<<<cdiv(N_*H_, T), T>>>();
    k_deg <<<cdiv(E_, T), T>>>(dstp);
    k_dinv<<<cdiv(N_, T), T>>>();
    sgemm<<<dim3(HID_/64, cdiv(N_, 64)), 256>>>(x, gcn_w, ph0, N_, HID_, 128,
                                                nullptr, nullptr, 0);
    k_gcn_self   <<<cdiv(N_*32, T), T>>>();
    k_gcn_scatter<<<cdiv(E_*32, T), T>>>(srcp, dstp);
    k_bias_relu  <<<cdiv(N_*HID_, T), T>>>(pacc, ph1, gcn_b, N_*HID_, HID_-1);

    // ---- GAT ----
    sgemm<<<dim3(H_*HID_/64, cdiv(N_, 64)), 256>>>(ph1, gat_w, pg, N_, H_*HID_, 128,
                                                   nullptr, nullptr, 0);
    k_att<<<cdiv(N_*H_, T), T>>>(att_s, att_d);
    k_e1 <<<cdiv(EP_, T), T>>>(srcp, dstp);
    k_decode_max<<<cdiv(N_*H_, T), T>>>();
    k_e2 <<<cdiv(EP_, T), T>>>(srcp, dstp);
    k_wden<<<cdiv(N_*H_, T), T>>>();
    k_agg_self   <<<cdiv(N_*32, T), T>>>();
    k_gat_scatter<<<cdiv(E_*32, T), T>>>(srcp, dstp);
    k_bias_relu  <<<cdiv(N_*HID_, T), T>>>(pagg, ph2, gat_b, N_*HID_, HID_-1);

    // ---- encoder MLP ----
    sgemm<<<dim3(2, cdiv(N_, 64)), 256>>>(ph2, w1, ph3, N_, HID_, 128, b1, nullptr, 1);
    sgemm<<<dim3(2, cdiv(N_, 64)), 256>>>(ph3, w2, ph4, N_, HID_, 128, b2, nullptr, 1);
    sgemm<<<dim3(1, cdiv(N_, 64)), 256>>>(ph4, mu_w, pmu, N_, Z_, 128, mu_b, nullptr, 0);
    sgemm<<<dim3(1, cdiv(N_, 64)), 256>>>(ph4, lv_w, plv, N_, Z_, 128, lv_b, nullptr, 0);

    // ---- reparameterize + write mu/logvar outputs ----
    int wr = ((size_t)out_size >= (size_t)N_*N_ + 2u*N_*Z_) ? 1 : 0;
    k_reparam<<<cdiv(N_*Z_, T), T>>>(eps, out + (size_t)N_*N_,
                                     out + (size_t)N_*N_ + (size_t)N_*Z_, wr);

    // ---- decoder ----
    sgemm<<<dim3(2, cdiv(N_, 64)), 256>>>(pz, dw1, pd1, N_, HID_, 64, db1, nullptr, 1);
    sgemm<<<dim3(1, cdiv(N_, 64)), 256>>>(pd1, dw2, pd, N_, Z_, 128, db2, pz, 0);

    // ---- logits = d @ d^T (symmetric, TF32 tensor cores, 3-term split) ----
    syrk_tf32<<<dim3(cdiv(N_, 128), cdiv(N_, 128)), 256>>>(pd, out);
}